// round 2
// baseline (speedup 1.0000x reference)
#include <cuda_runtime.h>
#include <stdint.h>

#define N_NODES 50000
#define D_FEAT  96
#define N_EDGES 800000

#define NBLOCKS 2048
#define NTHREADS 256
#define WARPS_PER_BLOCK (NTHREADS / 32)

// Scratch (no device allocation allowed in kernel_launch).
__device__ float g_partials[NBLOCKS];
__device__ int   g_is_i64;

// Detection: interpret the index buffer as int64; if any sampled value falls
// outside [0, N_NODES) the buffer must actually be int32 (JAX x64-disabled
// silently downcasts jnp.int64 -> int32). Deterministic, 1 thread.
__global__ void detect_index_dtype_kernel(const void* __restrict__ ei)
{
    const long long* p = (const long long*)ei;
    int ok = 1;
    #pragma unroll 1
    for (int i = 0; i < 64; i++) {
        long long v = p[i * 12345];   // spread samples across 2*N_EDGES entries
        if (v < 0 || v >= N_NODES) { ok = 0; break; }
    }
    g_is_i64 = ok;
}

// Kernel 1: warp-per-edge gather + L2-norm, block partial sums.
__global__ __launch_bounds__(NTHREADS)
void graph_smooth_edge_kernel(const float* __restrict__ feat,
                              const void* __restrict__ edge_index)
{
    const int lane    = threadIdx.x & 31;
    const int warpIn  = threadIdx.x >> 5;
    const int gwarp   = (blockIdx.x * NTHREADS + threadIdx.x) >> 5;
    const int nwarps  = (gridDim.x * NTHREADS) >> 5;

    const int is64 = g_is_i64;
    const long long* ei64 = (const long long*)edge_index;
    const int*       ei32 = (const int*)edge_index;

    float acc = 0.0f;  // lane 0 only

    for (int e = gwarp; e < N_EDGES; e += nwarps) {
        long long s, d;
        if (is64) {
            s = __ldg(ei64 + e);
            d = __ldg(ei64 + N_EDGES + e);
        } else {
            s = __ldg(ei32 + e);
            d = __ldg(ei32 + N_EDGES + e);
        }

        float part = 0.0f;
        if (lane < 24) {
            // row = 96 floats = 24 float4 = 384B (16B-aligned)
            const float4* ps = reinterpret_cast<const float4*>(feat + s * D_FEAT);
            const float4* pd = reinterpret_cast<const float4*>(feat + d * D_FEAT);
            float4 a = __ldg(ps + lane);
            float4 b = __ldg(pd + lane);
            float dx = a.x - b.x;
            float dy = a.y - b.y;
            float dz = a.z - b.z;
            float dw = a.w - b.w;
            part = dx * dx + dy * dy + dz * dz + dw * dw;
        }
        // full-warp reduce (lanes 24..31 contribute 0)
        #pragma unroll
        for (int off = 16; off > 0; off >>= 1)
            part += __shfl_down_sync(0xffffffffu, part, off);

        if (lane == 0)
            acc += sqrtf(part);
    }

    __shared__ float smem[WARPS_PER_BLOCK];
    if (lane == 0) smem[warpIn] = acc;
    __syncthreads();

    if (warpIn == 0) {
        float v = (lane < WARPS_PER_BLOCK) ? smem[lane] : 0.0f;
        #pragma unroll
        for (int off = 16; off > 0; off >>= 1)
            v += __shfl_down_sync(0xffffffffu, v, off);
        if (lane == 0) g_partials[blockIdx.x] = v;
    }
}

// Kernel 2: deterministic single-block reduction -> mean.
__global__ __launch_bounds__(NTHREADS)
void graph_smooth_final_kernel(float* __restrict__ out)
{
    const int tid  = threadIdx.x;
    const int lane = tid & 31;
    const int wid  = tid >> 5;

    float v = 0.0f;
    for (int i = tid; i < NBLOCKS; i += NTHREADS)
        v += g_partials[i];

    #pragma unroll
    for (int off = 16; off > 0; off >>= 1)
        v += __shfl_down_sync(0xffffffffu, v, off);

    __shared__ float smem[WARPS_PER_BLOCK];
    if (lane == 0) smem[wid] = v;
    __syncthreads();

    if (wid == 0) {
        float s = (lane < WARPS_PER_BLOCK) ? smem[lane] : 0.0f;
        #pragma unroll
        for (int off = 16; off > 0; off >>= 1)
            s += __shfl_down_sync(0xffffffffu, s, off);
        if (lane == 0)
            out[0] = s * (1.0f / (float)N_EDGES);  // WEIGHT = 1.0
    }
}

extern "C" void kernel_launch(void* const* d_in, const int* in_sizes, int n_in,
                              void* d_out, int out_size)
{
    const float* feat = (const float*)d_in[0];  // (50000, 96) f32
    const void*  ei   = d_in[1];                // (2, 800000) int64-or-int32
    float*       out  = (float*)d_out;          // scalar f32

    detect_index_dtype_kernel<<<1, 1>>>(ei);
    graph_smooth_edge_kernel<<<NBLOCKS, NTHREADS>>>(feat, ei);
    graph_smooth_final_kernel<<<1, NTHREADS>>>(out);
}

// round 3
// speedup vs baseline: 1.3788x; 1.3788x over previous
#include <cuda_runtime.h>
#include <cuda_fp16.h>
#include <stdint.h>

#define N_NODES 50000
#define D_FEAT  96
#define N_EDGES 800000

#define NBLOCKS 2048
#define NTHREADS 256
#define WARPS_PER_BLOCK (NTHREADS / 32)

// Scratch (device globals; no allocation allowed).
__device__ float g_partials[NBLOCKS];
__device__ int   g_is_i64;
__device__ __align__(16) __half g_feat_h[N_NODES * D_FEAT];  // 9.6 MB fp16 cache

// ---------------------------------------------------------------------------
// Dtype detection: one warp, 32 parallel samples, one ballot.
// If the buffer is really int32 (JAX x64-disabled), an int64 read fuses two
// int32 indices -> value >= 2^32 (unless hi word == 0, p ~ 1/50000 per sample).
__global__ void detect_index_dtype_kernel(const void* __restrict__ ei)
{
    const long long* p = (const long long*)ei;
    int t = threadIdx.x;                 // 0..31
    long long v = __ldg(p + (long long)t * 24691);   // max 765k < 800k slots
    unsigned bad = __ballot_sync(0xffffffffu, (v < 0) || (v >= N_NODES));
    if (t == 0) g_is_i64 = (bad == 0);
}

// ---------------------------------------------------------------------------
// f32 -> f16 feature conversion (streaming, ~29 MB total traffic).
__global__ __launch_bounds__(NTHREADS)
void convert_feat_kernel(const float* __restrict__ feat)
{
    const int n4 = (N_NODES * D_FEAT) / 4;   // 1.2M float4s
    uint2* __restrict__ dst = reinterpret_cast<uint2*>(g_feat_h);
    const float4* __restrict__ src = reinterpret_cast<const float4*>(feat);
    for (int i = blockIdx.x * blockDim.x + threadIdx.x; i < n4;
         i += gridDim.x * blockDim.x) {
        float4 v = __ldg(src + i);
        __half2 lo = __floats2half2_rn(v.x, v.y);
        __half2 hi = __floats2half2_rn(v.z, v.w);
        uint2 o;
        o.x = *reinterpret_cast<unsigned*>(&lo);
        o.y = *reinterpret_cast<unsigned*>(&hi);
        dst[i] = o;
    }
}

// squared diff of 2 halves packed in each of (a, b), accumulated in f32
__device__ __forceinline__ float sqdiff2(unsigned a, unsigned b)
{
    float2 fa = __half22float2(*reinterpret_cast<__half2*>(&a));
    float2 fb = __half22float2(*reinterpret_cast<__half2*>(&b));
    float dx = fa.x - fb.x;
    float dy = fa.y - fb.y;
    return dx * dx + dy * dy;
}

// ---------------------------------------------------------------------------
// Gather: half-warp per edge. Row = 96 halves = 192B = 12 x uint4.
__global__ __launch_bounds__(NTHREADS)
void graph_smooth_edge_kernel(const void* __restrict__ edge_index)
{
    const int lane   = threadIdx.x & 31;
    const int h      = lane & 15;       // lane within half-warp
    const int half   = lane >> 4;       // 0 or 1 -> which edge of the pair
    const int warpIn = threadIdx.x >> 5;
    const int gwarp  = (blockIdx.x * NTHREADS + threadIdx.x) >> 5;
    const int nwarps = (gridDim.x * NTHREADS) >> 5;

    const int is64 = g_is_i64;
    const long long* ei64 = (const long long*)edge_index;
    const int*       ei32 = (const int*)edge_index;

    float acc = 0.0f;   // meaningful in lanes 0 and 16

    // N_EDGES is even; e0 even => e0+1 < N_EDGES whenever e0 < N_EDGES.
    for (int e0 = gwarp * 2; e0 < N_EDGES; e0 += nwarps * 2) {
        const int e = e0 + half;

        long long s, d;
        if (is64) {
            s = __ldg(ei64 + e);
            d = __ldg(ei64 + N_EDGES + e);
        } else {
            s = __ldg(ei32 + e);
            d = __ldg(ei32 + N_EDGES + e);
        }

        float part = 0.0f;
        if (h < 12) {
            const uint4* ps = reinterpret_cast<const uint4*>(g_feat_h + s * D_FEAT);
            const uint4* pd = reinterpret_cast<const uint4*>(g_feat_h + d * D_FEAT);
            uint4 a = __ldg(ps + h);
            uint4 b = __ldg(pd + h);
            part  = sqdiff2(a.x, b.x);
            part += sqdiff2(a.y, b.y);
            part += sqdiff2(a.z, b.z);
            part += sqdiff2(a.w, b.w);
        }
        // reduce within each 16-lane group (lanes 12-15 contribute 0)
        #pragma unroll
        for (int off = 8; off > 0; off >>= 1)
            part += __shfl_down_sync(0xffffffffu, part, off, 16);

        if (h == 0)
            acc += sqrtf(part);
    }

    // combine the two half-warp accumulators, then block reduce
    acc += __shfl_down_sync(0xffffffffu, acc, 16);

    __shared__ float smem[WARPS_PER_BLOCK];
    if (lane == 0) smem[warpIn] = acc;
    __syncthreads();

    if (warpIn == 0) {
        float v = (lane < WARPS_PER_BLOCK) ? smem[lane] : 0.0f;
        #pragma unroll
        for (int off = 16; off > 0; off >>= 1)
            v += __shfl_down_sync(0xffffffffu, v, off);
        if (lane == 0) g_partials[blockIdx.x] = v;
    }
}

// ---------------------------------------------------------------------------
// Deterministic final reduction -> mean.
__global__ __launch_bounds__(NTHREADS)
void graph_smooth_final_kernel(float* __restrict__ out)
{
    const int tid  = threadIdx.x;
    const int lane = tid & 31;
    const int wid  = tid >> 5;

    float v = 0.0f;
    for (int i = tid; i < NBLOCKS; i += NTHREADS)
        v += g_partials[i];

    #pragma unroll
    for (int off = 16; off > 0; off >>= 1)
        v += __shfl_down_sync(0xffffffffu, v, off);

    __shared__ float smem[WARPS_PER_BLOCK];
    if (lane == 0) smem[wid] = v;
    __syncthreads();

    if (wid == 0) {
        float s = (lane < WARPS_PER_BLOCK) ? smem[lane] : 0.0f;
        #pragma unroll
        for (int off = 16; off > 0; off >>= 1)
            s += __shfl_down_sync(0xffffffffu, s, off);
        if (lane == 0)
            out[0] = s * (1.0f / (float)N_EDGES);  // WEIGHT = 1.0
    }
}

extern "C" void kernel_launch(void* const* d_in, const int* in_sizes, int n_in,
                              void* d_out, int out_size)
{
    const float* feat = (const float*)d_in[0];  // (50000, 96) f32
    const void*  ei   = d_in[1];                // (2, 800000) int64-or-int32
    float*       out  = (float*)d_out;          // scalar f32

    detect_index_dtype_kernel<<<1, 32>>>(ei);
    convert_feat_kernel<<<1024, NTHREADS>>>(feat);
    graph_smooth_edge_kernel<<<NBLOCKS, NTHREADS>>>(ei);
    graph_smooth_final_kernel<<<1, NTHREADS>>>(out);
}

// round 4
// speedup vs baseline: 1.4290x; 1.0364x over previous
#include <cuda_runtime.h>
#include <cuda_fp16.h>
#include <stdint.h>

#define N_NODES 50000
#define D_FEAT  96
#define N_EDGES 800000

#define NBLOCKS 2048
#define NTHREADS 256
#define WARPS_PER_BLOCK (NTHREADS / 32)
#define CONV_BLOCKS 1024

// Scratch (device globals; no allocation allowed).
__device__ float        g_partials[NBLOCKS];
__device__ int          g_is_i64;
__device__ unsigned int g_done_counter;
__device__ __align__(16) __half g_feat_h[N_NODES * D_FEAT];  // 9.6 MB fp16 cache

// ---------------------------------------------------------------------------
// Kernel A: f32 -> f16 feature conversion, fused with index-dtype detection
// and completion-counter reset (block 0, warp 0).
__global__ __launch_bounds__(NTHREADS)
void prep_kernel(const float* __restrict__ feat, const void* __restrict__ ei)
{
    if (blockIdx.x == 0 && threadIdx.x < 32) {
        // Detection: interpret buffer as int64; if really int32 (JAX x64
        // disabled), a fused pair of int32 indices lands outside [0, N_NODES).
        const long long* p = (const long long*)ei;
        int t = threadIdx.x;
        long long v = __ldg(p + (long long)t * 24691);   // samples < 800k slots
        unsigned bad = __ballot_sync(0xffffffffu, (v < 0) || (v >= N_NODES));
        if (t == 0) {
            g_is_i64 = (bad == 0);
            g_done_counter = 0u;          // reset for this launch (graph replay safe)
        }
    }

    const int n4 = (N_NODES * D_FEAT) / 4;   // 1.2M float4s
    uint2* __restrict__ dst = reinterpret_cast<uint2*>(g_feat_h);
    const float4* __restrict__ src = reinterpret_cast<const float4*>(feat);
    for (int i = blockIdx.x * blockDim.x + threadIdx.x; i < n4;
         i += gridDim.x * blockDim.x) {
        float4 v = __ldg(src + i);
        __half2 lo = __floats2half2_rn(v.x, v.y);
        __half2 hi = __floats2half2_rn(v.z, v.w);
        uint2 o;
        o.x = *reinterpret_cast<unsigned*>(&lo);
        o.y = *reinterpret_cast<unsigned*>(&hi);
        dst[i] = o;
    }
}

// squared diff of 2 halves packed in each of (a, b), accumulated in f32
__device__ __forceinline__ float sqdiff2(unsigned a, unsigned b)
{
    float2 fa = __half22float2(*reinterpret_cast<__half2*>(&a));
    float2 fb = __half22float2(*reinterpret_cast<__half2*>(&b));
    float dx = fa.x - fb.x;
    float dy = fa.y - fb.y;
    return dx * dx + dy * dy;
}

// ---------------------------------------------------------------------------
// Kernel B: half-warp-per-edge gather + L2-norm + block partials, with the
// final reduction fused via the last-block-done pattern (deterministic:
// exactly one block sums the fixed partials array in fixed order).
__global__ __launch_bounds__(NTHREADS)
void graph_smooth_edge_kernel(const void* __restrict__ edge_index,
                              float* __restrict__ out)
{
    const int lane   = threadIdx.x & 31;
    const int h      = lane & 15;       // lane within half-warp
    const int half   = lane >> 4;       // which edge of the pair
    const int warpIn = threadIdx.x >> 5;
    const int gwarp  = (blockIdx.x * NTHREADS + threadIdx.x) >> 5;
    const int nwarps = (gridDim.x * NTHREADS) >> 5;

    const int is64 = g_is_i64;
    const long long* ei64 = (const long long*)edge_index;
    const int*       ei32 = (const int*)edge_index;

    float acc = 0.0f;   // meaningful in lanes 0 and 16

    // N_EDGES even; e0 even => e0+1 < N_EDGES whenever e0 < N_EDGES.
    for (int e0 = gwarp * 2; e0 < N_EDGES; e0 += nwarps * 2) {
        const int e = e0 + half;

        long long s, d;
        if (is64) {
            s = __ldg(ei64 + e);
            d = __ldg(ei64 + N_EDGES + e);
        } else {
            s = __ldg(ei32 + e);
            d = __ldg(ei32 + N_EDGES + e);
        }

        float part = 0.0f;
        if (h < 12) {
            // row = 96 halves = 192B = 12 x uint4
            const uint4* ps = reinterpret_cast<const uint4*>(g_feat_h + s * D_FEAT);
            const uint4* pd = reinterpret_cast<const uint4*>(g_feat_h + d * D_FEAT);
            uint4 a = __ldg(ps + h);
            uint4 b = __ldg(pd + h);
            part  = sqdiff2(a.x, b.x);
            part += sqdiff2(a.y, b.y);
            part += sqdiff2(a.z, b.z);
            part += sqdiff2(a.w, b.w);
        }
        // reduce within each 16-lane group (lanes 12-15 contribute 0)
        #pragma unroll
        for (int off = 8; off > 0; off >>= 1)
            part += __shfl_down_sync(0xffffffffu, part, off, 16);

        if (h == 0)
            acc += sqrtf(part);
    }

    // combine the two half-warp accumulators, then block reduce
    acc += __shfl_down_sync(0xffffffffu, acc, 16);

    __shared__ float smem[WARPS_PER_BLOCK];
    __shared__ bool  amLast;
    if (lane == 0) smem[warpIn] = acc;
    __syncthreads();

    if (warpIn == 0) {
        float v = (lane < WARPS_PER_BLOCK) ? smem[lane] : 0.0f;
        #pragma unroll
        for (int off = 16; off > 0; off >>= 1)
            v += __shfl_down_sync(0xffffffffu, v, off);
        if (lane == 0) {
            g_partials[blockIdx.x] = v;
            __threadfence();
            unsigned prev = atomicAdd(&g_done_counter, 1u);
            amLast = (prev == NBLOCKS - 1);
        }
    }
    __syncthreads();

    // Last block to finish performs the deterministic final reduction.
    if (amLast) {
        const int tid = threadIdx.x;
        float v = 0.0f;
        #pragma unroll
        for (int i = 0; i < NBLOCKS / NTHREADS; i++)
            v += __ldcg(&g_partials[tid + i * NTHREADS]);

        #pragma unroll
        for (int off = 16; off > 0; off >>= 1)
            v += __shfl_down_sync(0xffffffffu, v, off);

        if (lane == 0) smem[warpIn] = v;
        __syncthreads();

        if (warpIn == 0) {
            float s = (lane < WARPS_PER_BLOCK) ? smem[lane] : 0.0f;
            #pragma unroll
            for (int off = 16; off > 0; off >>= 1)
                s += __shfl_down_sync(0xffffffffu, s, off);
            if (lane == 0)
                out[0] = s * (1.0f / (float)N_EDGES);  // WEIGHT = 1.0
        }
    }
}

extern "C" void kernel_launch(void* const* d_in, const int* in_sizes, int n_in,
                              void* d_out, int out_size)
{
    const float* feat = (const float*)d_in[0];  // (50000, 96) f32
    const void*  ei   = d_in[1];                // (2, 800000) int64-or-int32
    float*       out  = (float*)d_out;          // scalar f32

    prep_kernel<<<CONV_BLOCKS, NTHREADS>>>(feat, ei);
    graph_smooth_edge_kernel<<<NBLOCKS, NTHREADS>>>(ei, out);
}

// round 5
// speedup vs baseline: 1.8300x; 1.2806x over previous
#include <cuda_runtime.h>
#include <cuda_fp16.h>
#include <stdint.h>

#define N_NODES 50000
#define D_FEAT  96
#define N_EDGES 800000

#define NBLOCKS 2048
#define NTHREADS 256
#define WARPS_PER_BLOCK (NTHREADS / 32)
#define CONV_BLOCKS 1024
#define ROW_BYTES (D_FEAT * 2)   // 192 bytes per fp16 row

// Scratch (device globals; no allocation allowed).
__device__ float        g_partials[NBLOCKS];
__device__ int          g_is_i64;
__device__ unsigned int g_done_counter;
__device__ __align__(16) __half g_feat_h[N_NODES * D_FEAT];  // 9.6 MB fp16 cache

// ---------------------------------------------------------------------------
// Kernel A: f32 -> f16 conversion + index-dtype detection + counter reset.
__global__ __launch_bounds__(NTHREADS)
void prep_kernel(const float* __restrict__ feat, const void* __restrict__ ei)
{
    if (blockIdx.x == 0 && threadIdx.x < 32) {
        // If buffer is really int32 (JAX x64-disabled), an int64 read fuses
        // two int32 indices -> value outside [0, N_NODES).
        const long long* p = (const long long*)ei;
        int t = threadIdx.x;
        long long v = __ldg(p + (long long)t * 24691);
        unsigned bad = __ballot_sync(0xffffffffu, (v < 0) || (v >= N_NODES));
        if (t == 0) {
            g_is_i64 = (bad == 0);
            g_done_counter = 0u;     // graph-replay safe reset
        }
    }

    const int n4 = (N_NODES * D_FEAT) / 4;
    uint2* __restrict__ dst = reinterpret_cast<uint2*>(g_feat_h);
    const float4* __restrict__ src = reinterpret_cast<const float4*>(feat);
    for (int i = blockIdx.x * blockDim.x + threadIdx.x; i < n4;
         i += gridDim.x * blockDim.x) {
        float4 v = __ldg(src + i);
        __half2 lo = __floats2half2_rn(v.x, v.y);
        __half2 hi = __floats2half2_rn(v.z, v.w);
        uint2 o;
        o.x = *reinterpret_cast<unsigned*>(&lo);
        o.y = *reinterpret_cast<unsigned*>(&hi);
        dst[i] = o;
    }
}

__device__ __forceinline__ float sqrt_approx(float x)
{
    float r;
    asm("sqrt.approx.f32 %0, %1;" : "=f"(r) : "f"(x));
    return r;
}

// per-uint4 squared-diff accumulated in packed half2, returned as f32
__device__ __forceinline__ float sqdiff_u4(uint4 a, uint4 b)
{
    __half2 a0 = *reinterpret_cast<__half2*>(&a.x);
    __half2 a1 = *reinterpret_cast<__half2*>(&a.y);
    __half2 a2 = *reinterpret_cast<__half2*>(&a.z);
    __half2 a3 = *reinterpret_cast<__half2*>(&a.w);
    __half2 b0 = *reinterpret_cast<__half2*>(&b.x);
    __half2 b1 = *reinterpret_cast<__half2*>(&b.y);
    __half2 b2 = *reinterpret_cast<__half2*>(&b.z);
    __half2 b3 = *reinterpret_cast<__half2*>(&b.w);
    __half2 d0 = __hsub2(a0, b0);
    __half2 d1 = __hsub2(a1, b1);
    __half2 d2 = __hsub2(a2, b2);
    __half2 d3 = __hsub2(a3, b3);
    __half2 q0 = __hmul2(d0, d0);
    q0 = __hfma2(d1, d1, q0);          // each half slot: sum of 2 squares
    __half2 q1 = __hmul2(d2, d2);
    q1 = __hfma2(d3, d3, q1);
    float2 f0 = __half22float2(q0);
    float2 f1 = __half22float2(q1);
    return (f0.x + f0.y) + (f1.x + f1.y);
}

// ---------------------------------------------------------------------------
// Kernel B: half-warp-per-edge gather + norm + fused final reduction.
__global__ __launch_bounds__(NTHREADS)
void graph_smooth_edge_kernel(const void* __restrict__ edge_index,
                              float* __restrict__ out)
{
    const int lane   = threadIdx.x & 31;
    const int h      = lane & 15;       // lane within half-warp
    const int half_  = lane >> 4;       // which edge of the pair
    const int warpIn = threadIdx.x >> 5;
    const int gwarp  = (blockIdx.x * NTHREADS + threadIdx.x) >> 5;
    const int nwarps = (gridDim.x * NTHREADS) >> 5;

    const int is64 = g_is_i64;
    const long long* ei64 = (const long long*)edge_index;
    const int*       ei32 = (const int*)edge_index;
    const char* base = (const char*)g_feat_h;

    float acc = 0.0f;   // meaningful in lanes 0 and 16

    // N_EDGES even; e0 even => e0+1 < N_EDGES whenever e0 < N_EDGES.
    #pragma unroll 2
    for (int e0 = gwarp * 2; e0 < N_EDGES; e0 += nwarps * 2) {
        const int e = e0 + half_;

        int s, d;    // 32-bit index math (offsets < 9.6M)
        if (is64) {
            s = (int)__ldg(ei64 + e);
            d = (int)__ldg(ei64 + N_EDGES + e);
        } else {
            s = __ldg(ei32 + e);
            d = __ldg(ei32 + N_EDGES + e);
        }

        float part = 0.0f;
        if (h < 12) {
            // row = 96 halves = 192B = 12 x uint4
            const uint4* ps = reinterpret_cast<const uint4*>(base + (unsigned)s * ROW_BYTES);
            const uint4* pd = reinterpret_cast<const uint4*>(base + (unsigned)d * ROW_BYTES);
            uint4 a = __ldg(ps + h);
            uint4 b = __ldg(pd + h);
            part = sqdiff_u4(a, b);
        }
        // reduce within each 16-lane group (lanes 12-15 contribute 0)
        #pragma unroll
        for (int off = 8; off > 0; off >>= 1)
            part += __shfl_down_sync(0xffffffffu, part, off, 16);

        if (h == 0)
            acc += sqrt_approx(part);
    }

    // combine the two half-warp accumulators, then block reduce
    acc += __shfl_down_sync(0xffffffffu, acc, 16);

    __shared__ float smem[WARPS_PER_BLOCK];
    __shared__ bool  amLast;
    if (lane == 0) smem[warpIn] = acc;
    __syncthreads();

    if (warpIn == 0) {
        float v = (lane < WARPS_PER_BLOCK) ? smem[lane] : 0.0f;
        #pragma unroll
        for (int off = 16; off > 0; off >>= 1)
            v += __shfl_down_sync(0xffffffffu, v, off);
        if (lane == 0) {
            g_partials[blockIdx.x] = v;
            __threadfence();
            unsigned prev = atomicAdd(&g_done_counter, 1u);
            amLast = (prev == NBLOCKS - 1);
        }
    }
    __syncthreads();

    // Last block performs the deterministic final reduction (fixed order).
    if (amLast) {
        const int tid = threadIdx.x;
        float v = 0.0f;
        #pragma unroll
        for (int i = 0; i < NBLOCKS / NTHREADS; i++)
            v += __ldcg(&g_partials[tid + i * NTHREADS]);

        #pragma unroll
        for (int off = 16; off > 0; off >>= 1)
            v += __shfl_down_sync(0xffffffffu, v, off);

        if (lane == 0) smem[warpIn] = v;
        __syncthreads();

        if (warpIn == 0) {
            float s = (lane < WARPS_PER_BLOCK) ? smem[lane] : 0.0f;
            #pragma unroll
            for (int off = 16; off > 0; off >>= 1)
                s += __shfl_down_sync(0xffffffffu, s, off);
            if (lane == 0)
                out[0] = s * (1.0f / (float)N_EDGES);  // WEIGHT = 1.0
        }
    }
}

extern "C" void kernel_launch(void* const* d_in, const int* in_sizes, int n_in,
                              void* d_out, int out_size)
{
    const float* feat = (const float*)d_in[0];  // (50000, 96) f32
    const void*  ei   = d_in[1];                // (2, 800000) int64-or-int32
    float*       out  = (float*)d_out;          // scalar f32

    prep_kernel<<<CONV_BLOCKS, NTHREADS>>>(feat, ei);
    graph_smooth_edge_kernel<<<NBLOCKS, NTHREADS>>>(ei, out);
}

// round 6
// speedup vs baseline: 2.2367x; 1.2222x over previous
#include <cuda_runtime.h>
#include <cuda_fp16.h>
#include <stdint.h>

#define N_NODES 50000
#define D_FEAT  96
#define N_EDGES 800000

#define NBLOCKS 2048
#define NTHREADS 256
#define WARPS_PER_BLOCK (NTHREADS / 32)
#define CONV_BLOCKS 1024
#define ROW_BYTES (D_FEAT * 2)   // 192 bytes per fp16 row

// Scratch (device globals; no allocation allowed).
__device__ float        g_partials[NBLOCKS];
__device__ int          g_is_i64;
__device__ unsigned int g_done_counter;
__device__ __align__(16) __half g_feat_h[N_NODES * D_FEAT];  // 9.6 MB fp16 cache

// ---------------------------------------------------------------------------
// Kernel A: f32 -> f16 conversion + index-dtype detection + counter reset.
__global__ __launch_bounds__(NTHREADS)
void prep_kernel(const float* __restrict__ feat, const void* __restrict__ ei)
{
    if (blockIdx.x == 0 && threadIdx.x < 32) {
        // If buffer is really int32 (JAX x64-disabled), an int64 read fuses
        // two int32 indices -> value outside [0, N_NODES).
        const long long* p = (const long long*)ei;
        int t = threadIdx.x;
        long long v = __ldg(p + (long long)t * 24691);
        unsigned bad = __ballot_sync(0xffffffffu, (v < 0) || (v >= N_NODES));
        if (t == 0) {
            g_is_i64 = (bad == 0);
            g_done_counter = 0u;     // graph-replay safe reset
        }
    }

    const int n4 = (N_NODES * D_FEAT) / 4;
    uint2* __restrict__ dst = reinterpret_cast<uint2*>(g_feat_h);
    const float4* __restrict__ src = reinterpret_cast<const float4*>(feat);
    for (int i = blockIdx.x * blockDim.x + threadIdx.x; i < n4;
         i += gridDim.x * blockDim.x) {
        float4 v = __ldg(src + i);
        __half2 lo = __floats2half2_rn(v.x, v.y);
        __half2 hi = __floats2half2_rn(v.z, v.w);
        uint2 o;
        o.x = *reinterpret_cast<unsigned*>(&lo);
        o.y = *reinterpret_cast<unsigned*>(&hi);
        dst[i] = o;
    }
}

__device__ __forceinline__ float sqrt_approx(float x)
{
    float r;
    asm("sqrt.approx.f32 %0, %1;" : "=f"(r) : "f"(x));
    return r;
}

// accumulate squared diff of one uint4 pair into a packed half2 accumulator
__device__ __forceinline__ void sqdiff_acc(uint4 a, uint4 b, __half2& q)
{
    __half2 a0 = *reinterpret_cast<__half2*>(&a.x);
    __half2 a1 = *reinterpret_cast<__half2*>(&a.y);
    __half2 a2 = *reinterpret_cast<__half2*>(&a.z);
    __half2 a3 = *reinterpret_cast<__half2*>(&a.w);
    __half2 b0 = *reinterpret_cast<__half2*>(&b.x);
    __half2 b1 = *reinterpret_cast<__half2*>(&b.y);
    __half2 b2 = *reinterpret_cast<__half2*>(&b.z);
    __half2 b3 = *reinterpret_cast<__half2*>(&b.w);
    __half2 d0 = __hsub2(a0, b0);
    __half2 d1 = __hsub2(a1, b1);
    __half2 d2 = __hsub2(a2, b2);
    __half2 d3 = __hsub2(a3, b3);
    q = __hfma2(d0, d0, q);
    q = __hfma2(d1, d1, q);
    q = __hfma2(d2, d2, q);
    q = __hfma2(d3, d3, q);
}

// ---------------------------------------------------------------------------
// Kernel B: QUAD-per-edge gather + norm + fused final reduction.
// Each quad of 4 lanes handles one edge; lane j of the quad loads row slots
// {j, j+4, j+8} (each slot = uint4 = 16B; per-LDG a quad covers 64B contig).
__global__ __launch_bounds__(NTHREADS)
void graph_smooth_edge_kernel(const void* __restrict__ edge_index,
                              float* __restrict__ out)
{
    const int lane   = threadIdx.x & 31;
    const int q      = lane & 3;        // lane within quad
    const int quad   = lane >> 2;       // 0..7 -> which edge of the 8
    const int warpIn = threadIdx.x >> 5;
    const int gwarp  = (blockIdx.x * NTHREADS + threadIdx.x) >> 5;
    const int nwarps = (gridDim.x * NTHREADS) >> 5;

    const int is64 = g_is_i64;
    const long long* ei64 = (const long long*)edge_index;
    const int*       ei32 = (const int*)edge_index;
    const char* base = (const char*)g_feat_h;

    float acc = 0.0f;   // meaningful in quad-leader lanes (q == 0)

    // N_EDGES % 8 == 0, and warp strides cover groups of 8 edges.
    for (int e0 = gwarp * 8; e0 < N_EDGES; e0 += nwarps * 8) {
        const int e = e0 + quad;

        int s, d;    // 32-bit index math (byte offsets < 9.6M)
        if (is64) {
            s = (int)__ldg(ei64 + e);
            d = (int)__ldg(ei64 + N_EDGES + e);
        } else {
            s = __ldg(ei32 + e);
            d = __ldg(ei32 + N_EDGES + e);
        }

        const uint4* ps = reinterpret_cast<const uint4*>(base + (unsigned)s * ROW_BYTES);
        const uint4* pd = reinterpret_cast<const uint4*>(base + (unsigned)d * ROW_BYTES);

        // 6 independent loads -> good MLP
        uint4 a0 = __ldg(ps + q);
        uint4 b0 = __ldg(pd + q);
        uint4 a1 = __ldg(ps + q + 4);
        uint4 b1 = __ldg(pd + q + 4);
        uint4 a2 = __ldg(ps + q + 8);
        uint4 b2 = __ldg(pd + q + 8);

        __half2 qacc = __float2half2_rn(0.0f);
        sqdiff_acc(a0, b0, qacc);
        sqdiff_acc(a1, b1, qacc);
        sqdiff_acc(a2, b2, qacc);

        float2 f = __half22float2(qacc);
        float part = f.x + f.y;

        // reduce within quad (width 4)
        part += __shfl_down_sync(0xffffffffu, part, 2, 4);
        part += __shfl_down_sync(0xffffffffu, part, 1, 4);

        if (q == 0)
            acc += sqrt_approx(part);
    }

    // warp reduce (only q==0 lanes hold nonzero acc)
    #pragma unroll
    for (int off = 16; off > 0; off >>= 1)
        acc += __shfl_down_sync(0xffffffffu, acc, off);

    __shared__ float smem[WARPS_PER_BLOCK];
    __shared__ bool  amLast;
    if (lane == 0) smem[warpIn] = acc;
    __syncthreads();

    if (warpIn == 0) {
        float v = (lane < WARPS_PER_BLOCK) ? smem[lane] : 0.0f;
        #pragma unroll
        for (int off = 16; off > 0; off >>= 1)
            v += __shfl_down_sync(0xffffffffu, v, off);
        if (lane == 0) {
            g_partials[blockIdx.x] = v;
            __threadfence();
            unsigned prev = atomicAdd(&g_done_counter, 1u);
            amLast = (prev == NBLOCKS - 1);
        }
    }
    __syncthreads();

    // Last block performs the deterministic final reduction (fixed order).
    if (amLast) {
        const int tid = threadIdx.x;
        float v = 0.0f;
        #pragma unroll
        for (int i = 0; i < NBLOCKS / NTHREADS; i++)
            v += __ldcg(&g_partials[tid + i * NTHREADS]);

        #pragma unroll
        for (int off = 16; off > 0; off >>= 1)
            v += __shfl_down_sync(0xffffffffu, v, off);

        if (lane == 0) smem[warpIn] = v;
        __syncthreads();

        if (warpIn == 0) {
            float s = (lane < WARPS_PER_BLOCK) ? smem[lane] : 0.0f;
            #pragma unroll
            for (int off = 16; off > 0; off >>= 1)
                s += __shfl_down_sync(0xffffffffu, s, off);
            if (lane == 0)
                out[0] = s * (1.0f / (float)N_EDGES);  // WEIGHT = 1.0
        }
    }
}

extern "C" void kernel_launch(void* const* d_in, const int* in_sizes, int n_in,
                              void* d_out, int out_size)
{
    const float* feat = (const float*)d_in[0];  // (50000, 96) f32
    const void*  ei   = d_in[1];                // (2, 800000) int64-or-int32
    float*       out  = (float*)d_out;          // scalar f32

    prep_kernel<<<CONV_BLOCKS, NTHREADS>>>(feat, ei);
    graph_smooth_edge_kernel<<<NBLOCKS, NTHREADS>>>(ei, out);
}